// round 4
// baseline (speedup 1.0000x reference)
#include <cuda_runtime.h>
#include <cuda_bf16.h>

#define W 512
#define H 512
#define IMGS 128                       // 16 * 8
#define STRIP 32                       // output rows per warp
#define STRIPS (H / STRIP)             // 16
#define SEGS 2                         // column segments per row
#define SEGW 256                       // cols per warp segment
#define CPT 8                          // cols per thread
#define WARPS_TOTAL (IMGS * STRIPS * SEGS)   // 4096
#define BLOCK 256
#define WPB (BLOCK / 32)               // 8
#define GRID (WARPS_TOTAL / WPB)       // 512
#define NELEM 33554432.0f
#define FULLM 0xffffffffu

__device__ float g_partials[GRID];
__device__ unsigned int g_count;       // zero-init; last block resets

struct Carry {
    float xp[CPT];    // x[r-1] at this thread's cols
    float erp[CPT];   // er[r-1]
    float xLp, xRp;   // halo cols of x[r-1] (lane0 / lane31 only)
    float erpR;       // er[r-1][c1+1]     (lane31 only)
};

__device__ __forceinline__ void load8(const float* __restrict__ p, float x[CPT]) {
    float4 a = *reinterpret_cast<const float4*>(p);
    float4 b = *reinterpret_cast<const float4*>(p + 4);
    x[0]=a.x; x[1]=a.y; x[2]=a.z; x[3]=a.w;
    x[4]=b.x; x[5]=b.y; x[6]=b.z; x[7]=b.w;
}

// Load one row's worth for this thread: 8 main cols + predicated halo cols.
__device__ __forceinline__ void load_buf(const float* __restrict__ rowbase, int tcol,
                                         int lane, int cL, int cR, bool rightEdge,
                                         float x[CPT], float& xL, float& xR) {
    load8(rowbase + tcol, x);
    xL = (lane == 0)                ? __ldg(rowbase + cL) : 0.0f;
    xR = (!rightEdge && lane == 31) ? __ldg(rowbase + cR) : 0.0f;
}

// Consume (already-loaded) row r, emit loss for row r-1, advance carry.
__device__ __forceinline__ void step_compute(const float xc[CPT], float xLc, float xRc,
                                             int lane, bool rightEdge,
                                             Carry& C, float& acc) {
    float vm[CPT];
#pragma unroll
    for (int i = 0; i < CPT; i++) vm[i] = fminf(C.xp[i], xc[i]);  // vertical erosion
    float vmL = fminf(C.xLp, xLc);
    float vmR = fminf(C.xRp, xRc);

    // horizontal erosion: er[c] = min(vm[c-1], vm[c])
    float left = __shfl_up_sync(FULLM, vm[CPT-1], 1);
    if (lane == 0) left = vmL;                       // symmetric pad via cL clamp
    float ern[CPT];
    ern[0] = fminf(left, vm[0]);
#pragma unroll
    for (int i = 1; i < CPT; i++) ern[i] = fminf(vm[i-1], vm[i]);
    float ernR = fminf(vm[CPT-1], vmR);

    // vertical dilation for row r-1: h = max(er[r-1], er[r])
    float h[CPT];
#pragma unroll
    for (int i = 0; i < CPT; i++) h[i] = fmaxf(C.erp[i], ern[i]);
    float hR = fmaxf(C.erpR, ernR);

    // horizontal dilation + loss: di[c] = max(h[c], h[c+1])
    float hn = __shfl_down_sync(FULLM, h[0], 1);
    if (lane == 31) hn = rightEdge ? h[CPT-1] : hR;  // er[512]=er[511] at image edge
#pragma unroll
    for (int i = 0; i < CPT-1; i++) {
        float di = fmaxf(h[i], h[i+1]);
        float d = C.xp[i] - di;
        acc = fmaf(d, d, acc);
    }
    {
        float di = fmaxf(h[CPT-1], hn);
        float d = C.xp[CPT-1] - di;
        acc = fmaf(d, d, acc);
    }

#pragma unroll
    for (int i = 0; i < CPT; i++) { C.xp[i] = xc[i]; C.erp[i] = ern[i]; }
    C.xLp = xLc; C.xRp = xRc; C.erpR = ernR;
}

// Emit bottom image row (r = H-1): er[H] := er[H-1], so h == erp.
__device__ __forceinline__ void final_emit(int lane, bool rightEdge, Carry& C, float& acc) {
    float hn = __shfl_down_sync(FULLM, C.erp[0], 1);
    if (lane == 31) hn = rightEdge ? C.erp[CPT-1] : C.erpR;
#pragma unroll
    for (int i = 0; i < CPT-1; i++) {
        float di = fmaxf(C.erp[i], C.erp[i+1]);
        float d = C.xp[i] - di;
        acc = fmaf(d, d, acc);
    }
    float di = fmaxf(C.erp[CPT-1], hn);
    float d = C.xp[CPT-1] - di;
    acc = fmaf(d, d, acc);
}

__global__ void __launch_bounds__(BLOCK, 4)
opening_loss_kernel(const float* __restrict__ labels, float* __restrict__ out) {
    const int lane = threadIdx.x & 31;
    const int warp = blockIdx.x * WPB + (threadIdx.x >> 5);
    const int seg   = warp & (SEGS - 1);
    const int t     = warp >> 1;
    const int strip = t & (STRIPS - 1);
    const int img   = t >> 4;                        // STRIPS==16

    const float* base = labels + (size_t)img * (W * H);
    const int r0 = strip * STRIP;
    const int c0 = seg * SEGW;
    const bool rightEdge = (seg == SEGS - 1);
    const int cL = (c0 == 0) ? 0 : c0 - 1;           // clamp == symmetric pad
    const int cR = rightEdge ? (W - 1) : c0 + SEGW;
    const int tcol = c0 + lane * CPT;
    const bool lastStrip = (r0 + STRIP == H);

    Carry C;
    float acc = 0.0f;

    // Prologue: erp = er[r0], xp = x[r0]
    {
        const int rm1 = (r0 > 0) ? r0 - 1 : 0;       // x[-1]=x[0] pad
        const float* rowA = base + (size_t)rm1 * W;
        const float* rowB = base + (size_t)r0  * W;
        float xa[CPT], xb[CPT], xLa, xRa, xLb, xRb;
        load_buf(rowA, tcol, lane, cL, cR, rightEdge, xa, xLa, xRa);
        load_buf(rowB, tcol, lane, cL, cR, rightEdge, xb, xLb, xRb);

        float vm[CPT];
#pragma unroll
        for (int i = 0; i < CPT; i++) vm[i] = fminf(xa[i], xb[i]);
        float vmL = fminf(xLa, xLb);
        float vmR = fminf(xRa, xRb);

        float left = __shfl_up_sync(FULLM, vm[CPT-1], 1);
        if (lane == 0) left = vmL;
        C.erp[0] = fminf(left, vm[0]);
#pragma unroll
        for (int i = 1; i < CPT; i++) C.erp[i] = fminf(vm[i-1], vm[i]);
        C.erpR = fminf(vm[CPT-1], vmR);
#pragma unroll
        for (int i = 0; i < CPT; i++) C.xp[i] = xb[i];
        C.xLp = xLb; C.xRp = xRb;
    }

    // Software-pipelined stream: cx holds row r, nx prefetches row r+1.
    float cx[CPT], nx[CPT], cxL, cxR, nxL, nxR;
    load_buf(base + (size_t)(r0 + 1) * W, tcol, lane, cL, cR, rightEdge, cx, cxL, cxR);

    const int iters = lastStrip ? (STRIP - 1) : STRIP;   // rows r0+1 .. r0+iters
#pragma unroll 2
    for (int k = 0; k < iters; k++) {
        int rn = r0 + 2 + k;                             // prefetch row (clamped; dup ok)
        rn = (rn < H - 1) ? rn : (H - 1);
        load_buf(base + (size_t)rn * W, tcol, lane, cL, cR, rightEdge, nx, nxL, nxR);
        step_compute(cx, cxL, cxR, lane, rightEdge, C, acc);
#pragma unroll
        for (int i = 0; i < CPT; i++) cx[i] = nx[i];
        cxL = nxL; cxR = nxR;
    }
    if (lastStrip) final_emit(lane, rightEdge, C, acc);

    // Deterministic block reduction
#pragma unroll
    for (int off = 16; off; off >>= 1)
        acc += __shfl_xor_sync(FULLM, acc, off);

    __shared__ float s[WPB];
    __shared__ bool is_last;
    if (lane == 0) s[threadIdx.x >> 5] = acc;
    __syncthreads();
    if (threadIdx.x == 0) {
        float tsum = 0.0f;
#pragma unroll
        for (int i = 0; i < WPB; i++) tsum += s[i];
        g_partials[blockIdx.x] = tsum;
        __threadfence();
        unsigned v = atomicAdd(&g_count, 1u);
        is_last = (v == GRID - 1);
    }
    __syncthreads();

    // Last block: deterministic final tree reduction over 512 partials.
    if (is_last) {
        __shared__ float r[BLOCK];
        r[threadIdx.x] = g_partials[threadIdx.x] + g_partials[threadIdx.x + BLOCK];
        __syncthreads();
#pragma unroll
        for (int off = BLOCK / 2; off > 0; off >>= 1) {
            if (threadIdx.x < off) r[threadIdx.x] += r[threadIdx.x + off];
            __syncthreads();
        }
        if (threadIdx.x == 0) {
            out[0] = r[0] * (1.0f / NELEM);
            g_count = 0;    // reset for graph replay
        }
    }
}

extern "C" void kernel_launch(void* const* d_in, const int* in_sizes, int n_in,
                              void* d_out, int out_size) {
    const float* labels = (const float*)d_in[0];
    float* out = (float*)d_out;
    opening_loss_kernel<<<GRID, BLOCK>>>(labels, out);
}